// round 15
// baseline (speedup 1.0000x reference)
#include <cuda_runtime.h>
#include <cuda_fp16.h>
#include <cstdint>

#define NN 50000
#define NP 50048
#define NPH 50176          // 392 * 128 (gemm row tiles)
#define GT2 392
#define FF 128
#define EE 800000
#define NT2 6250           // EE / 128 (MLP tile = 128 edges)
#define MLP_CTAS 296
#define AGG_CTAS 1563

// ---------------- scratch (device globals; no allocation) ----------------
// INVARIANT: g_cnt, g_degf, g_bnsum are zero at kernel_launch entry.
__device__ float g_ew[3][EE];
__device__ int2  g_wpk[3][EE];
__device__ int   g_cnt[3][NN];
__device__ int   g_off[3][NN];
__device__ int   g_cur[3][NN];
__device__ float g_degf[3][NN];
__device__ uint32_t g_xwh[(size_t)NPH * 64];
__device__ float g_agg[(size_t)NP * FF];
__device__ float g_bnsum[4][FF];
__device__ uint32_t g_xh[(size_t)NN * 64];

__device__ __forceinline__ uint32_t pack_h2(float lo, float hi) {
    __half2 h = __floats2half2_rn(lo, hi);
    return *reinterpret_cast<uint32_t*>(&h);
}

__device__ __forceinline__ uint32_t habsdiff2(uint32_t a, uint32_t b) {
    __half2 ha = *reinterpret_cast<__half2*>(&a);
    __half2 hb = *reinterpret_cast<__half2*>(&b);
    __half2 d = __habs2(__hsub2(ha, hb));
    return *reinterpret_cast<uint32_t*>(&d);
}

__device__ __forceinline__ uint32_t smem_u32p(const void* p) {
    uint32_t a;
    asm("{ .reg .u64 t; cvta.to.shared.u64 t, %1; cvt.u32.u64 %0, t; }" : "=r"(a) : "l"(p));
    return a;
}

__device__ __forceinline__ void mma16(float* c, const uint32_t* a, uint32_t b0, uint32_t b1) {
    asm volatile(
        "mma.sync.aligned.m16n8k16.row.col.f32.f16.f16.f32 "
        "{%0,%1,%2,%3}, {%4,%5,%6,%7}, {%8,%9}, {%0,%1,%2,%3};"
        : "+f"(c[0]), "+f"(c[1]), "+f"(c[2]), "+f"(c[3])
        : "r"(a[0]), "r"(a[1]), "r"(a[2]), "r"(a[3]), "r"(b0), "r"(b1));
}

__device__ __forceinline__ void ldsm_x4(uint32_t* r, uint32_t addr) {
    asm volatile("ldmatrix.sync.aligned.m8n8.x4.shared.b16 {%0,%1,%2,%3}, [%4];"
        : "=r"(r[0]), "=r"(r[1]), "=r"(r[2]), "=r"(r[3]) : "r"(addr));
}

// ---------------- setup: xh convert + edge count (cnt pre-zeroed invariant) --
__global__ void k_init_count(const float* __restrict__ x,
                             const int* __restrict__ e0, const int* __restrict__ e1,
                             const int* __restrict__ e2) {
    int i = blockIdx.x * blockDim.x + threadIdx.x;
    if (i < NN * 64) {
        float2 v = ((const float2*)x)[i];
        g_xh[i] = pack_h2(v.x, v.y);
    }
    if (i < 3 * EE) {
        int s = i / EE, j = i - s * EE;
        const int* col = (s == 0 ? e0 : s == 1 ? e1 : e2) + EE;
        atomicAdd(&g_cnt[s][col[j]], 1);
    }
}

// ---------------- exclusive scan of cnt -> off/cur ---------------------------
__global__ void k_scan() {
    __shared__ int wsum[32];
    __shared__ int carry;
    int s = blockIdx.x;
    int tid = threadIdx.x;
    int l = tid & 31, w = tid >> 5;
    if (tid == 0) carry = 0;
    __syncthreads();
    for (int base = 0; base < NN; base += 1024) {
        int i = base + tid;
        int v = (i < NN) ? g_cnt[s][i] : 0;
        int x = v;
#pragma unroll
        for (int off = 1; off < 32; off <<= 1) {
            int t = __shfl_up_sync(0xffffffffu, x, off);
            if (l >= off) x += t;
        }
        if (l == 31) wsum[w] = x;
        __syncthreads();
        if (w == 0) {
            int y = wsum[l];
#pragma unroll
            for (int off = 1; off < 32; off <<= 1) {
                int t = __shfl_up_sync(0xffffffffu, y, off);
                if (l >= off) y += t;
            }
            wsum[l] = y;
        }
        __syncthreads();
        int excl = carry + (w > 0 ? wsum[w - 1] : 0) + x - v;
        if (i < NN) {
            g_off[s][i] = excl;
            g_cur[s][i] = excl;
        }
        __syncthreads();
        if (tid == 0) carry += wsum[31];
        __syncthreads();
    }
}

// ---------------- edge MLP: 256 threads, 2 CTAs/SM, tile = 128 edges ----------
// kb-loop A-fragments software-pipelined (prefetch kb+1 during kb's B+MMA)
#define EW_SMEM_U32 (8704 + 8704 + 128 + 128 + 128)
#define EW_SMEM_BYTES (EW_SMEM_U32 * 4)   // 71168 B

__global__ void __launch_bounds__(256, 2) k_edge_mlp_mma(
    const int* __restrict__ e0, const int* __restrict__ e1, const int* __restrict__ e2,
    const float* __restrict__ Wa1, const float* __restrict__ ba1,
    const float* __restrict__ Wa2, const float* __restrict__ ba2) {
    extern __shared__ uint32_t sm[];
    uint32_t* As = sm;
    uint32_t* Ws = sm + 8704;
    float* Bb = (float*)(sm + 17408);
    float* W2 = (float*)(sm + 17536);
    float* ped = (float*)(sm + 17664);
    const uint32_t smA = smem_u32p(As);
    const uint32_t smW = smem_u32p(Ws);

    const int tid = threadIdx.x;
    const int w = tid >> 5, l = tid & 31;
    const int g = l >> 2, t = l & 3;
    const int rg = w & 3, cg = w >> 2;
    const int rowbase = rg * 32;

    const int ge = (w << 1) + (l >> 4);
    const int q = l & 15;

    const int arow0 = rowbase + ((l >> 3) & 1) * 8 + (l & 7);
    const int acb = (l >> 4) << 2;
    const int am0base = arow0 * 68, am0rot = acb + 8 * arow0;
    const int am1base = (arow0 + 16) * 68, am1rot = acb + 8 * (arow0 + 16);
    int hb4[4];
#pragma unroll
    for (int j = 0; j < 4; ++j)
        hb4[j] = ((cg * 8 + 2 * j + ((l >> 4) & 1)) * 8 + (l & 7)) * 68 + (((l >> 3) & 1) << 2);

    for (int set = 0; set < 3; ++set) {
        const int* ei = (set == 0) ? e0 : (set == 1) ? e1 : e2;
        __syncthreads();
        {
            const float* W = Wa1 + set * 16384;
            int h = tid >> 1, hf = tid & 1;
            const float4* src = (const float4*)(W + h * 128 + hf * 64);
            uint32_t* dst = Ws + h * 68 + hf * 32;
#pragma unroll
            for (int i2 = 0; i2 < 16; ++i2) {
                float4 v = src[i2];
                dst[2 * i2]     = pack_h2(v.x, v.y);
                dst[2 * i2 + 1] = pack_h2(v.z, v.w);
            }
            if (tid < 128) {
                Bb[tid] = ba1[set * 128 + tid];
                W2[tid] = Wa2[set * 128 + tid];
            }
        }
        const float b2 = ba2[set];
        __syncthreads();

        for (int tile = blockIdx.x; tile < NT2; tile += MLP_CTAS) {
            const int eb = tile * 128;
#pragma unroll
            for (int j = 0; j < 8; ++j) {
                int me = j * 16 + ge;
                int r = ei[eb + me];
                int c = ei[EE + eb + me];
                uint4 va = ((const uint4*)(g_xh + (size_t)r * 64))[q];
                uint4 vb = ((const uint4*)(g_xh + (size_t)c * 64))[q];
                uint4 d;
                d.x = habsdiff2(va.x, vb.x);
                d.y = habsdiff2(va.y, vb.y);
                d.z = habsdiff2(va.z, vb.z);
                d.w = habsdiff2(va.w, vb.w);
                *(uint4*)(As + me * 68 + ((4 * q + 8 * me) & 63)) = d;
            }
            __syncthreads();

            float acc[2][8][4];
#pragma unroll
            for (int mb = 0; mb < 2; ++mb)
#pragma unroll
                for (int nb = 0; nb < 8; ++nb)
#pragma unroll
                    for (int qq = 0; qq < 4; ++qq) acc[mb][nb][qq] = 0.f;

            // software-pipelined A fragments across kb
            uint32_t af0[2][4], af1[2][4];
            ldsm_x4(af0[0], smA + 4u * (am0base + (am0rot & 63)));
            ldsm_x4(af1[0], smA + 4u * (am1base + (am1rot & 63)));
#pragma unroll
            for (int kb = 0; kb < 8; ++kb) {
                const int cur = kb & 1, nxt = cur ^ 1;
                if (kb < 7) {
                    ldsm_x4(af0[nxt], smA + 4u * (am0base + ((8 * (kb + 1) + am0rot) & 63)));
                    ldsm_x4(af1[nxt], smA + 4u * (am1base + ((8 * (kb + 1) + am1rot) & 63)));
                }
#pragma unroll
                for (int j = 0; j < 4; ++j) {
                    uint32_t bf[4];
                    ldsm_x4(bf, smW + 4u * (hb4[j] + 8 * kb));
                    mma16(acc[0][2 * j],     af0[cur], bf[0], bf[1]);
                    mma16(acc[0][2 * j + 1], af0[cur], bf[2], bf[3]);
                    mma16(acc[1][2 * j],     af1[cur], bf[0], bf[1]);
                    mma16(acc[1][2 * j + 1], af1[cur], bf[2], bf[3]);
                }
            }

            float s[4] = {0.f, 0.f, 0.f, 0.f};
#pragma unroll
            for (int nb = 0; nb < 8; ++nb) {
                int h0 = (cg * 8 + nb) * 8 + 2 * t;
                float bb0 = Bb[h0], bb1 = Bb[h0 + 1];
                float w20 = W2[h0], w21 = W2[h0 + 1];
                s[0] += fmaxf(acc[0][nb][0] + bb0, 0.f) * w20 + fmaxf(acc[0][nb][1] + bb1, 0.f) * w21;
                s[1] += fmaxf(acc[0][nb][2] + bb0, 0.f) * w20 + fmaxf(acc[0][nb][3] + bb1, 0.f) * w21;
                s[2] += fmaxf(acc[1][nb][0] + bb0, 0.f) * w20 + fmaxf(acc[1][nb][1] + bb1, 0.f) * w21;
                s[3] += fmaxf(acc[1][nb][2] + bb0, 0.f) * w20 + fmaxf(acc[1][nb][3] + bb1, 0.f) * w21;
            }
#pragma unroll
            for (int i = 0; i < 4; ++i) {
                s[i] += __shfl_xor_sync(0xffffffffu, s[i], 1);
                s[i] += __shfl_xor_sync(0xffffffffu, s[i], 2);
            }
            int r0 = rowbase + g;
            if (cg == 1 && t == 0) {
                ped[r0]      = s[0];
                ped[r0 + 8]  = s[1];
                ped[r0 + 16] = s[2];
                ped[r0 + 24] = s[3];
            }
            __syncthreads();
            if (cg == 0 && t == 0) {
#pragma unroll
                for (int i = 0; i < 4; ++i) {
                    int rr = r0 + i * 8;
                    float z = s[i] + ped[rr] + b2;
                    float sig = 1.f / (1.f + expf(-z));
                    g_ew[set][eb + rr] = sig;
                    atomicAdd(&g_degf[set][ei[EE + eb + rr]], sig);
                }
            }
        }
    }
}

// ---------------- node GEMM layer0 (plain, 296 CTAs) -------------------------
#define GM_SMEM_U32 (8704 + 8704 + 512)
#define GM_SMEM_BYTES (GM_SMEM_U32 * 4)   // 71680 B

__global__ void __launch_bounds__(256, 2) k_gemm0(const float* __restrict__ W) {
    extern __shared__ uint32_t sm[];
    uint32_t* As = sm;
    uint32_t* Ws = sm + 8704;
    const uint32_t smA = smem_u32p(As);
    const uint32_t smW = smem_u32p(Ws);

    const int tid = threadIdx.x;
    const int w = tid >> 5, l = tid & 31;
    const int g = l >> 2, t = l & 3;
    const int rg = w & 3, cg = w >> 2;
    const int rowbase = rg * 32;

    {
        int h = tid >> 1, hf = tid & 1;
        const float4* src = (const float4*)(W + h * 128 + hf * 64);
        uint32_t* dst = Ws + h * 68 + hf * 32;
#pragma unroll
        for (int i2 = 0; i2 < 16; ++i2) {
            float4 v = src[i2];
            dst[2 * i2]     = pack_h2(v.x, v.y);
            dst[2 * i2 + 1] = pack_h2(v.z, v.w);
        }
    }
    __syncthreads();

    const int ge = (w << 1) + (l >> 4);
    const int q = l & 15;
    const int arow0 = rowbase + ((l >> 3) & 1) * 8 + (l & 7);
    const int acb = (l >> 4) << 2;
    const int am0base = arow0 * 68, am0rot = acb + 8 * arow0;
    const int am1base = (arow0 + 16) * 68, am1rot = acb + 8 * (arow0 + 16);
    int hb4[4];
#pragma unroll
    for (int j = 0; j < 4; ++j)
        hb4[j] = ((cg * 8 + 2 * j + ((l >> 4) & 1)) * 8 + (l & 7)) * 68 + (((l >> 3) & 1) << 2);

    for (int tile = blockIdx.x; tile < GT2; tile += MLP_CTAS) {
        const int rb = tile * 128;
#pragma unroll
        for (int j = 0; j < 8; ++j) {
            int m = j * 16 + ge;
            int row = rb + m;
            uint4 d = make_uint4(0, 0, 0, 0);
            if (row < NN) d = ((const uint4*)(g_xh + (size_t)row * 64))[q];
            *(uint4*)(As + m * 68 + ((4 * q + 8 * m) & 63)) = d;
        }
        __syncthreads();

        float acc[2][8][4];
#pragma unroll
        for (int mb = 0; mb < 2; ++mb)
#pragma unroll
            for (int nb = 0; nb < 8; ++nb)
#pragma unroll
                for (int qq = 0; qq < 4; ++qq) acc[mb][nb][qq] = 0.f;

#pragma unroll
        for (int kb = 0; kb < 8; ++kb) {
            uint32_t af0[4], af1[4];
            ldsm_x4(af0, smA + 4u * (am0base + ((8 * kb + am0rot) & 63)));
            ldsm_x4(af1, smA + 4u * (am1base + ((8 * kb + am1rot) & 63)));
#pragma unroll
            for (int j = 0; j < 4; ++j) {
                uint32_t bf[4];
                ldsm_x4(bf, smW + 4u * (hb4[j] + 8 * kb));
                mma16(acc[0][2 * j],     af0, bf[0], bf[1]);
                mma16(acc[0][2 * j + 1], af0, bf[2], bf[3]);
                mma16(acc[1][2 * j],     af1, bf[0], bf[1]);
                mma16(acc[1][2 * j + 1], af1, bf[2], bf[3]);
            }
        }

#pragma unroll
        for (int mb = 0; mb < 2; ++mb) {
#pragma unroll
            for (int nb = 0; nb < 8; ++nb) {
                int grow = rb + rowbase + mb * 16 + g;
                int col = cg * 32 + nb * 4 + t;
                g_xwh[(size_t)grow * 64 + col] = pack_h2(acc[mb][nb][0], acc[mb][nb][1]);
                g_xwh[(size_t)(grow + 8) * 64 + col] = pack_h2(acc[mb][nb][2], acc[mb][nb][3]);
            }
        }
        __syncthreads();
    }
}

// ---------------- CSR fill -----------------------------------------------------
__global__ void k_fill(const int* __restrict__ e0, const int* __restrict__ e1,
                       const int* __restrict__ e2) {
    int i = blockIdx.x * blockDim.x + threadIdx.x;
    if (i >= 3 * EE) return;
    int s = i / EE, j = i - s * EE;
    const int* E = (s == 0 ? e0 : s == 1 ? e1 : e2);
    int row = E[j], col = E[EE + j];
    int pos = atomicAdd(&g_cur[s][col], 1);
    float dgr = g_degf[s][row];
    float wt = g_ew[s][j] * (dgr > 0.f ? rsqrtf(dgr) : 0.f);
    g_wpk[s][pos] = make_int2(row, __float_as_int(wt));
}

// ---------------- gemm layer1: inline BN-finalize + BN-apply + relu on load --
__global__ void __launch_bounds__(256, 2) k_gemm1(
    const float* __restrict__ W, const float* __restrict__ gamma,
    const float* __restrict__ beta) {
    extern __shared__ uint32_t sm[];
    uint32_t* As = sm;
    uint32_t* Ws = sm + 8704;
    float* P = (float*)(sm + 17408);
    const uint32_t smA = smem_u32p(As);
    const uint32_t smW = smem_u32p(Ws);

    const int tid = threadIdx.x;
    const int w = tid >> 5, l = tid & 31;
    const int g = l >> 2, t = l & 3;
    const int rg = w & 3, cg = w >> 2;
    const int rowbase = rg * 32;

    {
        int h = tid >> 1, hf = tid & 1;
        const float4* src = (const float4*)(W + h * 128 + hf * 64);
        uint32_t* dst = Ws + h * 68 + hf * 32;
#pragma unroll
        for (int i2 = 0; i2 < 16; ++i2) {
            float4 v = src[i2];
            dst[2 * i2]     = pack_h2(v.x, v.y);
            dst[2 * i2 + 1] = pack_h2(v.z, v.w);
        }
    }
    if (tid < 128) {
        float mu = g_bnsum[0][tid] / (float)NN;
        float var = g_bnsum[1][tid] / (float)NN - mu * mu;
        P[tid]       = mu;
        P[128 + tid] = rsqrtf(var + 1e-5f);
        P[256 + tid] = gamma[tid];
        P[384 + tid] = beta[tid];
    }
    if (blockIdx.x == 0 && tid < 256) (&g_bnsum[2][0])[tid] = 0.f;
    __syncthreads();

    const int arow0 = rowbase + ((l >> 3) & 1) * 8 + (l & 7);
    const int acb = (l >> 4) << 2;
    const int am0base = arow0 * 68, am0rot = acb + 8 * arow0;
    const int am1base = (arow0 + 16) * 68, am1rot = acb + 8 * (arow0 + 16);
    int hb4[4];
#pragma unroll
    for (int j = 0; j < 4; ++j)
        hb4[j] = ((cg * 8 + 2 * j + ((l >> 4) & 1)) * 8 + (l & 7)) * 68 + (((l >> 3) & 1) << 2);

    for (int tile = blockIdx.x; tile < GT2; tile += MLP_CTAS) {
        const int rb = tile * 128;
        {
            int c0 = l * 4;
            float mu0 = P[c0], mu1 = P[c0 + 1], mu2 = P[c0 + 2], mu3 = P[c0 + 3];
            float rs0 = P[128 + c0], rs1 = P[129 + c0], rs2 = P[130 + c0], rs3 = P[131 + c0];
            float ga0 = P[256 + c0], ga1 = P[257 + c0], ga2 = P[258 + c0], ga3 = P[259 + c0];
            float be0 = P[384 + c0], be1 = P[385 + c0], be2 = P[386 + c0], be3 = P[387 + c0];
#pragma unroll
            for (int j = 0; j < 16; ++j) {
                int m = w * 16 + j;
                int row = rb + m;
                uint2 d = make_uint2(0, 0);
                if (row < NN) {
                    float4 v = *(const float4*)(g_agg + (size_t)row * 128 + c0);
                    float a0 = fmaxf((v.x - mu0) * rs0 * ga0 + be0, 0.f);
                    float a1 = fmaxf((v.y - mu1) * rs1 * ga1 + be1, 0.f);
                    float a2 = fmaxf((v.z - mu2) * rs2 * ga2 + be2, 0.f);
                    float a3 = fmaxf((v.w - mu3) * rs3 * ga3 + be3, 0.f);
                    d.x = pack_h2(a0, a1);
                    d.y = pack_h2(a2, a3);
                }
                *(uint2*)(As + m * 68 + ((2 * l + 8 * m) & 63)) = d;
            }
        }
        __syncthreads();

        float acc[2][8][4];
#pragma unroll
        for (int mb = 0; mb < 2; ++mb)
#pragma unroll
            for (int nb = 0; nb < 8; ++nb)
#pragma unroll
                for (int qq = 0; qq < 4; ++qq) acc[mb][nb][qq] = 0.f;

#pragma unroll
        for (int kb = 0; kb < 8; ++kb) {
            uint32_t af0[4], af1[4];
            ldsm_x4(af0, smA + 4u * (am0base + ((8 * kb + am0rot) & 63)));
            ldsm_x4(af1, smA + 4u * (am1base + ((8 * kb + am1rot) & 63)));
#pragma unroll
            for (int j = 0; j < 4; ++j) {
                uint32_t bf[4];
                ldsm_x4(bf, smW + 4u * (hb4[j] + 8 * kb));
                mma16(acc[0][2 * j],     af0, bf[0], bf[1]);
                mma16(acc[0][2 * j + 1], af0, bf[2], bf[3]);
                mma16(acc[1][2 * j],     af1, bf[0], bf[1]);
                mma16(acc[1][2 * j + 1], af1, bf[2], bf[3]);
            }
        }

#pragma unroll
        for (int mb = 0; mb < 2; ++mb) {
#pragma unroll
            for (int nb = 0; nb < 8; ++nb) {
                int grow = rb + rowbase + mb * 16 + g;
                int col = cg * 32 + nb * 4 + t;
                g_xwh[(size_t)grow * 64 + col] = pack_h2(acc[mb][nb][0], acc[mb][nb][1]);
                g_xwh[(size_t)(grow + 8) * 64 + col] = pack_h2(acc[mb][nb][2], acc[mb][nb][3]);
            }
        }
        __syncthreads();
    }
}

// ---------------- aggregation: 2-way unrolled gather (MLP=2) -----------------
__global__ void __launch_bounds__(256) k_agg(const float* __restrict__ bias, int layer) {
    __shared__ float st[256];
    int tid = threadIdx.x;
    st[tid] = 0.f;
    __syncthreads();

    int wg = (blockIdx.x * 256 + tid) >> 5;
    int lane = tid & 31;
    int c0 = lane * 4;
    float b0 = 3.f * bias[c0], b1 = 3.f * bias[c0 + 1];
    float b2 = 3.f * bias[c0 + 2], b3 = 3.f * bias[c0 + 3];
    float4 ss = make_float4(0, 0, 0, 0), sq = make_float4(0, 0, 0, 0);

    for (int n = wg; n < NN; n += AGG_CTAS * 8) {
        float4 acc = make_float4(0, 0, 0, 0);
#pragma unroll
        for (int s = 0; s < 3; ++s) {
            int c = g_cnt[s][n];
            if (c == 0) continue;
            int o = g_off[s][n];
            float dc = rsqrtf(g_degf[s][n]);
            const int2* wp = &g_wpk[s][o];
            float4 pa = make_float4(0, 0, 0, 0);
            float4 pb = make_float4(0, 0, 0, 0);
            int k = 0;
            for (; k + 2 <= c; k += 2) {
                int2 rw0 = wp[k];
                int2 rw1 = wp[k + 1];
                uint2 v0 = *(const uint2*)(g_xwh + (size_t)rw0.x * 64 + lane * 2);
                uint2 v1 = *(const uint2*)(g_xwh + (size_t)rw1.x * 64 + lane * 2);
                float wt0 = __int_as_float(rw0.y);
                float wt1 = __int_as_float(rw1.y);
                float2 a0 = __half22float2(*reinterpret_cast<__half2*>(&v0.x));
                float2 a1 = __half22float2(*reinterpret_cast<__half2*>(&v0.y));
                float2 b0f = __half22float2(*reinterpret_cast<__half2*>(&v1.x));
                float2 b1f = __half22float2(*reinterpret_cast<__half2*>(&v1.y));
                pa.x = fmaf(wt0, a0.x, pa.x);
                pa.y = fmaf(wt0, a0.y, pa.y);
                pa.z = fmaf(wt0, a1.x, pa.z);
                pa.w = fmaf(wt0, a1.y, pa.w);
                pb.x = fmaf(wt1, b0f.x, pb.x);
                pb.y = fmaf(wt1, b0f.y, pb.y);
                pb.z = fmaf(wt1, b1f.x, pb.z);
                pb.w = fmaf(wt1, b1f.y, pb.w);
            }
            if (k < c) {
                int2 rw0 = wp[k];
                uint2 v0 = *(const uint2*)(g_xwh + (size_t)rw0.x * 64 + lane * 2);
                float wt0 = __int_as_float(rw0.y);
                float2 a0 = __half22float2(*reinterpret_cast<__half2*>(&v0.x));
                float2 a1 = __half22float2(*reinterpret_cast<__half2*>(&v0.y));
                pa.x = fmaf(wt0, a0.x, pa.x);
                pa.y = fmaf(wt0, a0.y, pa.y);
                pa.z = fmaf(wt0, a1.x, pa.z);
                pa.w = fmaf(wt0, a1.y, pa.w);
            }
            pa.x += pb.x; pa.y += pb.y; pa.z += pb.z; pa.w += pb.w;
            acc.x = fmaf(dc, pa.x, acc.x);
            acc.y = fmaf(dc, pa.y, acc.y);
            acc.z = fmaf(dc, pa.z, acc.z);
            acc.w = fmaf(dc, pa.w, acc.w);
        }
        float4 v;
        v.x = fmaxf(acc.x + b0, 0.f);
        v.y = fmaxf(acc.y + b1, 0.f);
        v.z = fmaxf(acc.z + b2, 0.f);
        v.w = fmaxf(acc.w + b3, 0.f);
        *(float4*)(g_agg + (size_t)n * 128 + c0) = v;
        ss.x += v.x; ss.y += v.y; ss.z += v.z; ss.w += v.w;
        sq.x += v.x * v.x; sq.y += v.y * v.y; sq.z += v.z * v.z; sq.w += v.w * v.w;
    }
    atomicAdd(&st[c0 + 0], ss.x);
    atomicAdd(&st[c0 + 1], ss.y);
    atomicAdd(&st[c0 + 2], ss.z);
    atomicAdd(&st[c0 + 3], ss.w);
    atomicAdd(&st[128 + c0 + 0], sq.x);
    atomicAdd(&st[128 + c0 + 1], sq.y);
    atomicAdd(&st[128 + c0 + 2], sq.z);
    atomicAdd(&st[128 + c0 + 3], sq.w);
    __syncthreads();
    if (tid < 128) atomicAdd(&g_bnsum[2 * layer][tid], st[tid]);
    else atomicAdd(&g_bnsum[2 * layer + 1][tid - 128], st[tid]);
}

// ---------------- final: inline BN-finalize + apply + residual + tail zeroing
__global__ void k_final(const float* __restrict__ x, const float* __restrict__ gamma,
                        const float* __restrict__ beta, float* __restrict__ out) {
    __shared__ float P[256];
    int tid = threadIdx.x;
    int i = blockIdx.x * blockDim.x + tid;
    if (tid < 128) {
        float mu = g_bnsum[2][tid] / (float)NN;
        float var = g_bnsum[3][tid] / (float)NN - mu * mu;
        P[tid]       = mu;
        P[128 + tid] = rsqrtf(var + 1e-5f);
    }
    __syncthreads();
    if (i < NN * 32) {
        int cb = (i & 31) * 4;
        float4 v = ((const float4*)g_agg)[i];
        float4 xv = ((const float4*)x)[i];
        v.x = (v.x - P[cb + 0]) * P[128 + cb + 0] * gamma[cb + 0] + beta[cb + 0] + xv.x;
        v.y = (v.y - P[cb + 1]) * P[128 + cb + 1] * gamma[cb + 1] + beta[cb + 1] + xv.y;
        v.z = (v.z - P[cb + 2]) * P[128 + cb + 2] * gamma[cb + 2] + beta[cb + 2] + xv.z;
        v.w = (v.w - P[cb + 3]) * P[128 + cb + 3] * gamma[cb + 3] + beta[cb + 3] + xv.w;
        ((float4*)out)[i] = v;
    }
    if (i < 3 * NN) {
        (&g_cnt[0][0])[i] = 0;
        (&g_degf[0][0])[i] = 0.f;
    }
    if (i < 256) (&g_bnsum[0][0])[i] = 0.f;
}

// ---------------- launch ----------------
extern "C" void kernel_launch(void* const* d_in, const int* in_sizes, int n_in,
                              void* d_out, int out_size) {
    const float* x   = (const float*)d_in[0];
    const int*   e0  = (const int*)d_in[1];
    const int*   e1  = (const int*)d_in[2];
    const int*   e2  = (const int*)d_in[3];
    const float* Wa1 = (const float*)d_in[4];
    const float* ba1 = (const float*)d_in[5];
    const float* Wa2 = (const float*)d_in[6];
    const float* ba2 = (const float*)d_in[7];
    const float* W0  = (const float*)d_in[8];
    const float* b0  = (const float*)d_in[9];
    const float* W1  = (const float*)d_in[10];
    const float* b1  = (const float*)d_in[11];
    const float* g0  = (const float*)d_in[12];
    const float* be0 = (const float*)d_in[13];
    const float* g1  = (const float*)d_in[14];
    const float* be1 = (const float*)d_in[15];
    float* out = (float*)d_out;

    cudaFuncSetAttribute(k_edge_mlp_mma, cudaFuncAttributeMaxDynamicSharedMemorySize,
                         EW_SMEM_BYTES);
    cudaFuncSetAttribute(k_gemm0, cudaFuncAttributeMaxDynamicSharedMemorySize,
                         GM_SMEM_BYTES);
    cudaFuncSetAttribute(k_gemm1, cudaFuncAttributeMaxDynamicSharedMemorySize,
                         GM_SMEM_BYTES);

    k_init_count<<<(NN * 64 + 255) / 256, 256>>>(x, e0, e1, e2);
    k_edge_mlp_mma<<<MLP_CTAS, 256, EW_SMEM_BYTES>>>(e0, e1, e2, Wa1, ba1, Wa2, ba2);
    k_scan<<<3, 1024>>>();
    k_gemm0<<<MLP_CTAS, 256, GM_SMEM_BYTES>>>(W0);
    k_fill<<<(3 * EE + 255) / 256, 256>>>(e0, e1, e2);

    k_agg<<<AGG_CTAS, 256>>>(b0, 0);
    k_gemm1<<<MLP_CTAS, 256, GM_SMEM_BYTES>>>(W1, g0, be0);
    k_agg<<<AGG_CTAS, 256>>>(b1, 1);
    k_final<<<(NN * 32 + 255) / 256, 256>>>(x, g1, be1, out);
}

// round 16
// speedup vs baseline: 1.0535x; 1.0535x over previous
#include <cuda_runtime.h>
#include <cuda_fp16.h>
#include <cstdint>

#define NN 50000
#define NP 50048
#define NPH 50176          // 392 * 128 (gemm row tiles)
#define GT2 392
#define FF 128
#define EE 800000
#define NT2 6250           // EE / 128 (MLP tile = 128 edges)
#define MLP_CTAS 296
#define AGG_CTAS 1563

// ---------------- scratch (device globals; no allocation) ----------------
// INVARIANT: g_cnt, g_degf, g_bnsum are zero at kernel_launch entry.
__device__ float g_ew[3][EE];
__device__ int2  g_wpk[3][EE];
__device__ int   g_cnt[3][NN];
__device__ int   g_off[3][NN];
__device__ int   g_cur[3][NN];
__device__ float g_degf[3][NN];
__device__ uint32_t g_xwh[(size_t)NPH * 64];
__device__ float g_agg[(size_t)NP * FF];
__device__ float g_bnsum[4][FF];
__device__ uint32_t g_xh[(size_t)NN * 64];

__device__ __forceinline__ uint32_t pack_h2(float lo, float hi) {
    __half2 h = __floats2half2_rn(lo, hi);
    return *reinterpret_cast<uint32_t*>(&h);
}

__device__ __forceinline__ uint32_t habsdiff2(uint32_t a, uint32_t b) {
    __half2 ha = *reinterpret_cast<__half2*>(&a);
    __half2 hb = *reinterpret_cast<__half2*>(&b);
    __half2 d = __habs2(__hsub2(ha, hb));
    return *reinterpret_cast<uint32_t*>(&d);
}

__device__ __forceinline__ uint32_t smem_u32p(const void* p) {
    uint32_t a;
    asm("{ .reg .u64 t; cvta.to.shared.u64 t, %1; cvt.u32.u64 %0, t; }" : "=r"(a) : "l"(p));
    return a;
}

__device__ __forceinline__ void mma16(float* c, const uint32_t* a, uint32_t b0, uint32_t b1) {
    asm volatile(
        "mma.sync.aligned.m16n8k16.row.col.f32.f16.f16.f32 "
        "{%0,%1,%2,%3}, {%4,%5,%6,%7}, {%8,%9}, {%0,%1,%2,%3};"
        : "+f"(c[0]), "+f"(c[1]), "+f"(c[2]), "+f"(c[3])
        : "r"(a[0]), "r"(a[1]), "r"(a[2]), "r"(a[3]), "r"(b0), "r"(b1));
}

__device__ __forceinline__ void ldsm_x4(uint32_t* r, uint32_t addr) {
    asm volatile("ldmatrix.sync.aligned.m8n8.x4.shared.b16 {%0,%1,%2,%3}, [%4];"
        : "=r"(r[0]), "=r"(r[1]), "=r"(r[2]), "=r"(r[3]) : "r"(addr));
}

// ---------------- xh convert ----------------
__global__ void k_xh(const float* __restrict__ x) {
    int i = blockIdx.x * blockDim.x + threadIdx.x;
    if (i < NN * 64) {
        float2 v = ((const float2*)x)[i];
        g_xh[i] = pack_h2(v.x, v.y);
    }
}

// ---------------- edge count (cnt pre-zeroed invariant; side stream) --------
__global__ void k_count(const int* __restrict__ e0, const int* __restrict__ e1,
                        const int* __restrict__ e2) {
    int i = blockIdx.x * blockDim.x + threadIdx.x;
    if (i >= 3 * EE) return;
    int s = i / EE, j = i - s * EE;
    const int* col = (s == 0 ? e0 : s == 1 ? e1 : e2) + EE;
    atomicAdd(&g_cnt[s][col[j]], 1);
}

// ---------------- exclusive scan of cnt -> off/cur ---------------------------
__global__ void k_scan() {
    __shared__ int wsum[32];
    __shared__ int carry;
    int s = blockIdx.x;
    int tid = threadIdx.x;
    int l = tid & 31, w = tid >> 5;
    if (tid == 0) carry = 0;
    __syncthreads();
    for (int base = 0; base < NN; base += 1024) {
        int i = base + tid;
        int v = (i < NN) ? g_cnt[s][i] : 0;
        int x = v;
#pragma unroll
        for (int off = 1; off < 32; off <<= 1) {
            int t = __shfl_up_sync(0xffffffffu, x, off);
            if (l >= off) x += t;
        }
        if (l == 31) wsum[w] = x;
        __syncthreads();
        if (w == 0) {
            int y = wsum[l];
#pragma unroll
            for (int off = 1; off < 32; off <<= 1) {
                int t = __shfl_up_sync(0xffffffffu, y, off);
                if (l >= off) y += t;
            }
            wsum[l] = y;
        }
        __syncthreads();
        int excl = carry + (w > 0 ? wsum[w - 1] : 0) + x - v;
        if (i < NN) {
            g_off[s][i] = excl;
            g_cur[s][i] = excl;
        }
        __syncthreads();
        if (tid == 0) carry += wsum[31];
        __syncthreads();
    }
}

// ---------------- edge MLP: 256 threads, 2 CTAs/SM, tile = 128 edges ----------
#define EW_SMEM_U32 (8704 + 8704 + 128 + 128 + 128)
#define EW_SMEM_BYTES (EW_SMEM_U32 * 4)   // 71168 B

__global__ void __launch_bounds__(256, 2) k_edge_mlp_mma(
    const int* __restrict__ e0, const int* __restrict__ e1, const int* __restrict__ e2,
    const float* __restrict__ Wa1, const float* __restrict__ ba1,
    const float* __restrict__ Wa2, const float* __restrict__ ba2) {
    extern __shared__ uint32_t sm[];
    uint32_t* As = sm;
    uint32_t* Ws = sm + 8704;
    float* Bb = (float*)(sm + 17408);
    float* W2 = (float*)(sm + 17536);
    float* ped = (float*)(sm + 17664);
    const uint32_t smA = smem_u32p(As);
    const uint32_t smW = smem_u32p(Ws);

    const int tid = threadIdx.x;
    const int w = tid >> 5, l = tid & 31;
    const int g = l >> 2, t = l & 3;
    const int rg = w & 3, cg = w >> 2;
    const int rowbase = rg * 32;

    const int ge = (w << 1) + (l >> 4);
    const int q = l & 15;

    const int arow0 = rowbase + ((l >> 3) & 1) * 8 + (l & 7);
    const int acb = (l >> 4) << 2;
    const int am0base = arow0 * 68, am0rot = acb + 8 * arow0;
    const int am1base = (arow0 + 16) * 68, am1rot = acb + 8 * (arow0 + 16);
    int hb4[4];
#pragma unroll
    for (int j = 0; j < 4; ++j)
        hb4[j] = ((cg * 8 + 2 * j + ((l >> 4) & 1)) * 8 + (l & 7)) * 68 + (((l >> 3) & 1) << 2);

    for (int set = 0; set < 3; ++set) {
        const int* ei = (set == 0) ? e0 : (set == 1) ? e1 : e2;
        __syncthreads();
        {
            const float* W = Wa1 + set * 16384;
            int h = tid >> 1, hf = tid & 1;
            const float4* src = (const float4*)(W + h * 128 + hf * 64);
            uint32_t* dst = Ws + h * 68 + hf * 32;
#pragma unroll
            for (int i2 = 0; i2 < 16; ++i2) {
                float4 v = src[i2];
                dst[2 * i2]     = pack_h2(v.x, v.y);
                dst[2 * i2 + 1] = pack_h2(v.z, v.w);
            }
            if (tid < 128) {
                Bb[tid] = ba1[set * 128 + tid];
                W2[tid] = Wa2[set * 128 + tid];
            }
        }
        const float b2 = ba2[set];
        __syncthreads();

        for (int tile = blockIdx.x; tile < NT2; tile += MLP_CTAS) {
            const int eb = tile * 128;
#pragma unroll
            for (int j = 0; j < 8; ++j) {
                int me = j * 16 + ge;
                int r = ei[eb + me];
                int c = ei[EE + eb + me];
                uint4 va = ((const uint4*)(g_xh + (size_t)r * 64))[q];
                uint4 vb = ((const uint4*)(g_xh + (size_t)c * 64))[q];
                uint4 d;
                d.x = habsdiff2(va.x, vb.x);
                d.y = habsdiff2(va.y, vb.y);
                d.z = habsdiff2(va.z, vb.z);
                d.w = habsdiff2(va.w, vb.w);
                *(uint4*)(As + me * 68 + ((4 * q + 8 * me) & 63)) = d;
            }
            __syncthreads();

            float acc[2][8][4];
#pragma unroll
            for (int mb = 0; mb < 2; ++mb)
#pragma unroll
                for (int nb = 0; nb < 8; ++nb)
#pragma unroll
                    for (int qq = 0; qq < 4; ++qq) acc[mb][nb][qq] = 0.f;

            uint32_t af0[2][4], af1[2][4];
            ldsm_x4(af0[0], smA + 4u * (am0base + (am0rot & 63)));
            ldsm_x4(af1[0], smA + 4u * (am1base + (am1rot & 63)));
#pragma unroll
            for (int kb = 0; kb < 8; ++kb) {
                const int cur = kb & 1, nxt = cur ^ 1;
                if (kb < 7) {
                    ldsm_x4(af0[nxt], smA + 4u * (am0base + ((8 * (kb + 1) + am0rot) & 63)));
                    ldsm_x4(af1[nxt], smA + 4u * (am1base + ((8 * (kb + 1) + am1rot) & 63)));
                }
#pragma unroll
                for (int j = 0; j < 4; ++j) {
                    uint32_t bf[4];
                    ldsm_x4(bf, smW + 4u * (hb4[j] + 8 * kb));
                    mma16(acc[0][2 * j],     af0[cur], bf[0], bf[1]);
                    mma16(acc[0][2 * j + 1], af0[cur], bf[2], bf[3]);
                    mma16(acc[1][2 * j],     af1[cur], bf[0], bf[1]);
                    mma16(acc[1][2 * j + 1], af1[cur], bf[2], bf[3]);
                }
            }

            float s[4] = {0.f, 0.f, 0.f, 0.f};
#pragma unroll
            for (int nb = 0; nb < 8; ++nb) {
                int h0 = (cg * 8 + nb) * 8 + 2 * t;
                float bb0 = Bb[h0], bb1 = Bb[h0 + 1];
                float w20 = W2[h0], w21 = W2[h0 + 1];
                s[0] += fmaxf(acc[0][nb][0] + bb0, 0.f) * w20 + fmaxf(acc[0][nb][1] + bb1, 0.f) * w21;
                s[1] += fmaxf(acc[0][nb][2] + bb0, 0.f) * w20 + fmaxf(acc[0][nb][3] + bb1, 0.f) * w21;
                s[2] += fmaxf(acc[1][nb][0] + bb0, 0.f) * w20 + fmaxf(acc[1][nb][1] + bb1, 0.f) * w21;
                s[3] += fmaxf(acc[1][nb][2] + bb0, 0.f) * w20 + fmaxf(acc[1][nb][3] + bb1, 0.f) * w21;
            }
#pragma unroll
            for (int i = 0; i < 4; ++i) {
                s[i] += __shfl_xor_sync(0xffffffffu, s[i], 1);
                s[i] += __shfl_xor_sync(0xffffffffu, s[i], 2);
            }
            int r0 = rowbase + g;
            if (cg == 1 && t == 0) {
                ped[r0]      = s[0];
                ped[r0 + 8]  = s[1];
                ped[r0 + 16] = s[2];
                ped[r0 + 24] = s[3];
            }
            __syncthreads();
            if (cg == 0 && t == 0) {
#pragma unroll
                for (int i = 0; i < 4; ++i) {
                    int rr = r0 + i * 8;
                    float z = s[i] + ped[rr] + b2;
                    float sig = 1.f / (1.f + expf(-z));
                    g_ew[set][eb + rr] = sig;
                    atomicAdd(&g_degf[set][ei[EE + eb + rr]], sig);
                }
            }
        }
    }
}

// ---------------- node GEMM layer0 (side stream) -----------------------------
#define GM_SMEM_U32 (8704 + 8704 + 512)
#define GM_SMEM_BYTES (GM_SMEM_U32 * 4)   // 71680 B

__global__ void __launch_bounds__(256, 2) k_gemm0(const float* __restrict__ W) {
    extern __shared__ uint32_t sm[];
    uint32_t* As = sm;
    uint32_t* Ws = sm + 8704;
    const uint32_t smA = smem_u32p(As);
    const uint32_t smW = smem_u32p(Ws);

    const int tid = threadIdx.x;
    const int w = tid >> 5, l = tid & 31;
    const int g = l >> 2, t = l & 3;
    const int rg = w & 3, cg = w >> 2;
    const int rowbase = rg * 32;

    {
        int h = tid >> 1, hf = tid & 1;
        const float4* src = (const float4*)(W + h * 128 + hf * 64);
        uint32_t* dst = Ws + h * 68 + hf * 32;
#pragma unroll
        for (int i2 = 0; i2 < 16; ++i2) {
            float4 v = src[i2];
            dst[2 * i2]     = pack_h2(v.x, v.y);
            dst[2 * i2 + 1] = pack_h2(v.z, v.w);
        }
    }
    __syncthreads();

    const int ge = (w << 1) + (l >> 4);
    const int q = l & 15;
    const int arow0 = rowbase + ((l >> 3) & 1) * 8 + (l & 7);
    const int acb = (l >> 4) << 2;
    const int am0base = arow0 * 68, am0rot = acb + 8 * arow0;
    const int am1base = (arow0 + 16) * 68, am1rot = acb + 8 * (arow0 + 16);
    int hb4[4];
#pragma unroll
    for (int j = 0; j < 4; ++j)
        hb4[j] = ((cg * 8 + 2 * j + ((l >> 4) & 1)) * 8 + (l & 7)) * 68 + (((l >> 3) & 1) << 2);

    for (int tile = blockIdx.x; tile < GT2; tile += MLP_CTAS) {
        const int rb = tile * 128;
#pragma unroll
        for (int j = 0; j < 8; ++j) {
            int m = j * 16 + ge;
            int row = rb + m;
            uint4 d = make_uint4(0, 0, 0, 0);
            if (row < NN) d = ((const uint4*)(g_xh + (size_t)row * 64))[q];
            *(uint4*)(As + m * 68 + ((4 * q + 8 * m) & 63)) = d;
        }
        __syncthreads();

        float acc[2][8][4];
#pragma unroll
        for (int mb = 0; mb < 2; ++mb)
#pragma unroll
            for (int nb = 0; nb < 8; ++nb)
#pragma unroll
                for (int qq = 0; qq < 4; ++qq) acc[mb][nb][qq] = 0.f;

#pragma unroll
        for (int kb = 0; kb < 8; ++kb) {
            uint32_t af0[4], af1[4];
            ldsm_x4(af0, smA + 4u * (am0base + ((8 * kb + am0rot) & 63)));
            ldsm_x4(af1, smA + 4u * (am1base + ((8 * kb + am1rot) & 63)));
#pragma unroll
            for (int j = 0; j < 4; ++j) {
                uint32_t bf[4];
                ldsm_x4(bf, smW + 4u * (hb4[j] + 8 * kb));
                mma16(acc[0][2 * j],     af0, bf[0], bf[1]);
                mma16(acc[0][2 * j + 1], af0, bf[2], bf[3]);
                mma16(acc[1][2 * j],     af1, bf[0], bf[1]);
                mma16(acc[1][2 * j + 1], af1, bf[2], bf[3]);
            }
        }

#pragma unroll
        for (int mb = 0; mb < 2; ++mb) {
#pragma unroll
            for (int nb = 0; nb < 8; ++nb) {
                int grow = rb + rowbase + mb * 16 + g;
                int col = cg * 32 + nb * 4 + t;
                g_xwh[(size_t)grow * 64 + col] = pack_h2(acc[mb][nb][0], acc[mb][nb][1]);
                g_xwh[(size_t)(grow + 8) * 64 + col] = pack_h2(acc[mb][nb][2], acc[mb][nb][3]);
            }
        }
        __syncthreads();
    }
}

// ---------------- CSR fill -----------------------------------------------------
__global__ void k_fill(const int* __restrict__ e0, const int* __restrict__ e1,
                       const int* __restrict__ e2) {
    int i = blockIdx.x * blockDim.x + threadIdx.x;
    if (i >= 3 * EE) return;
    int s = i / EE, j = i - s * EE;
    const int* E = (s == 0 ? e0 : s == 1 ? e1 : e2);
    int row = E[j], col = E[EE + j];
    int pos = atomicAdd(&g_cur[s][col], 1);
    float dgr = g_degf[s][row];
    float wt = g_ew[s][j] * (dgr > 0.f ? rsqrtf(dgr) : 0.f);
    g_wpk[s][pos] = make_int2(row, __float_as_int(wt));
}

// ---------------- gemm layer1: inline BN-finalize + BN-apply + relu on load --
__global__ void __launch_bounds__(256, 2) k_gemm1(
    const float* __restrict__ W, const float* __restrict__ gamma,
    const float* __restrict__ beta) {
    extern __shared__ uint32_t sm[];
    uint32_t* As = sm;
    uint32_t* Ws = sm + 8704;
    float* P = (float*)(sm + 17408);
    const uint32_t smA = smem_u32p(As);
    const uint32_t smW = smem_u32p(Ws);

    const int tid = threadIdx.x;
    const int w = tid >> 5, l = tid & 31;
    const int g = l >> 2, t = l & 3;
    const int rg = w & 3, cg = w >> 2;
    const int rowbase = rg * 32;

    {
        int h = tid >> 1, hf = tid & 1;
        const float4* src = (const float4*)(W + h * 128 + hf * 64);
        uint32_t* dst = Ws + h * 68 + hf * 32;
#pragma unroll
        for (int i2 = 0; i2 < 16; ++i2) {
            float4 v = src[i2];
            dst[2 * i2]     = pack_h2(v.x, v.y);
            dst[2 * i2 + 1] = pack_h2(v.z, v.w);
        }
    }
    if (tid < 128) {
        float mu = g_bnsum[0][tid] / (float)NN;
        float var = g_bnsum[1][tid] / (float)NN - mu * mu;
        P[tid]       = mu;
        P[128 + tid] = rsqrtf(var + 1e-5f);
        P[256 + tid] = gamma[tid];
        P[384 + tid] = beta[tid];
    }
    if (blockIdx.x == 0 && tid < 256) (&g_bnsum[2][0])[tid] = 0.f;
    __syncthreads();

    const int arow0 = rowbase + ((l >> 3) & 1) * 8 + (l & 7);
    const int acb = (l >> 4) << 2;
    const int am0base = arow0 * 68, am0rot = acb + 8 * arow0;
    const int am1base = (arow0 + 16) * 68, am1rot = acb + 8 * (arow0 + 16);
    int hb4[4];
#pragma unroll
    for (int j = 0; j < 4; ++j)
        hb4[j] = ((cg * 8 + 2 * j + ((l >> 4) & 1)) * 8 + (l & 7)) * 68 + (((l >> 3) & 1) << 2);

    for (int tile = blockIdx.x; tile < GT2; tile += MLP_CTAS) {
        const int rb = tile * 128;
        {
            int c0 = l * 4;
            float mu0 = P[c0], mu1 = P[c0 + 1], mu2 = P[c0 + 2], mu3 = P[c0 + 3];
            float rs0 = P[128 + c0], rs1 = P[129 + c0], rs2 = P[130 + c0], rs3 = P[131 + c0];
            float ga0 = P[256 + c0], ga1 = P[257 + c0], ga2 = P[258 + c0], ga3 = P[259 + c0];
            float be0 = P[384 + c0], be1 = P[385 + c0], be2 = P[386 + c0], be3 = P[387 + c0];
#pragma unroll
            for (int j = 0; j < 16; ++j) {
                int m = w * 16 + j;
                int row = rb + m;
                uint2 d = make_uint2(0, 0);
                if (row < NN) {
                    float4 v = *(const float4*)(g_agg + (size_t)row * 128 + c0);
                    float a0 = fmaxf((v.x - mu0) * rs0 * ga0 + be0, 0.f);
                    float a1 = fmaxf((v.y - mu1) * rs1 * ga1 + be1, 0.f);
                    float a2 = fmaxf((v.z - mu2) * rs2 * ga2 + be2, 0.f);
                    float a3 = fmaxf((v.w - mu3) * rs3 * ga3 + be3, 0.f);
                    d.x = pack_h2(a0, a1);
                    d.y = pack_h2(a2, a3);
                }
                *(uint2*)(As + m * 68 + ((2 * l + 8 * m) & 63)) = d;
            }
        }
        __syncthreads();

        float acc[2][8][4];
#pragma unroll
        for (int mb = 0; mb < 2; ++mb)
#pragma unroll
            for (int nb = 0; nb < 8; ++nb)
#pragma unroll
                for (int qq = 0; qq < 4; ++qq) acc[mb][nb][qq] = 0.f;

#pragma unroll
        for (int kb = 0; kb < 8; ++kb) {
            uint32_t af0[4], af1[4];
            ldsm_x4(af0, smA + 4u * (am0base + ((8 * kb + am0rot) & 63)));
            ldsm_x4(af1, smA + 4u * (am1base + ((8 * kb + am1rot) & 63)));
#pragma unroll
            for (int j = 0; j < 4; ++j) {
                uint32_t bf[4];
                ldsm_x4(bf, smW + 4u * (hb4[j] + 8 * kb));
                mma16(acc[0][2 * j],     af0, bf[0], bf[1]);
                mma16(acc[0][2 * j + 1], af0, bf[2], bf[3]);
                mma16(acc[1][2 * j],     af1, bf[0], bf[1]);
                mma16(acc[1][2 * j + 1], af1, bf[2], bf[3]);
            }
        }

#pragma unroll
        for (int mb = 0; mb < 2; ++mb) {
#pragma unroll
            for (int nb = 0; nb < 8; ++nb) {
                int grow = rb + rowbase + mb * 16 + g;
                int col = cg * 32 + nb * 4 + t;
                g_xwh[(size_t)grow * 64 + col] = pack_h2(acc[mb][nb][0], acc[mb][nb][1]);
                g_xwh[(size_t)(grow + 8) * 64 + col] = pack_h2(acc[mb][nb][2], acc[mb][nb][3]);
            }
        }
        __syncthreads();
    }
}

// ---------------- aggregation: 2-way unrolled gather -------------------------
__global__ void __launch_bounds__(256) k_agg(const float* __restrict__ bias, int layer) {
    __shared__ float st[256];
    int tid = threadIdx.x;
    st[tid] = 0.f;
    __syncthreads();

    int wg = (blockIdx.x * 256 + tid) >> 5;
    int lane = tid & 31;
    int c0 = lane * 4;
    float b0 = 3.f * bias[c0], b1 = 3.f * bias[c0 + 1];
    float b2 = 3.f * bias[c0 + 2], b3 = 3.f * bias[c0 + 3];
    float4 ss = make_float4(0, 0, 0, 0), sq = make_float4(0, 0, 0, 0);

    for (int n = wg; n < NN; n += AGG_CTAS * 8) {
        float4 acc = make_float4(0, 0, 0, 0);
#pragma unroll
        for (int s = 0; s < 3; ++s) {
            int c = g_cnt[s][n];
            if (c == 0) continue;
            int o = g_off[s][n];
            float dc = rsqrtf(g_degf[s][n]);
            const int2* wp = &g_wpk[s][o];
            float4 pa = make_float4(0, 0, 0, 0);
            float4 pb = make_float4(0, 0, 0, 0);
            int k = 0;
            for (; k + 2 <= c; k += 2) {
                int2 rw0 = wp[k];
                int2 rw1 = wp[k + 1];
                uint2 v0 = *(const uint2*)(g_xwh + (size_t)rw0.x * 64 + lane * 2);
                uint2 v1 = *(const uint2*)(g_xwh + (size_t)rw1.x * 64 + lane * 2);
                float wt0 = __int_as_float(rw0.y);
                float wt1 = __int_as_float(rw1.y);
                float2 a0 = __half22float2(*reinterpret_cast<__half2*>(&v0.x));
                float2 a1 = __half22float2(*reinterpret_cast<__half2*>(&v0.y));
                float2 b0f = __half22float2(*reinterpret_cast<__half2*>(&v1.x));
                float2 b1f = __half22float2(*reinterpret_cast<__half2*>(&v1.y));
                pa.x = fmaf(wt0, a0.x, pa.x);
                pa.y = fmaf(wt0, a0.y, pa.y);
                pa.z = fmaf(wt0, a1.x, pa.z);
                pa.w = fmaf(wt0, a1.y, pa.w);
                pb.x = fmaf(wt1, b0f.x, pb.x);
                pb.y = fmaf(wt1, b0f.y, pb.y);
                pb.z = fmaf(wt1, b1f.x, pb.z);
                pb.w = fmaf(wt1, b1f.y, pb.w);
            }
            if (k < c) {
                int2 rw0 = wp[k];
                uint2 v0 = *(const uint2*)(g_xwh + (size_t)rw0.x * 64 + lane * 2);
                float wt0 = __int_as_float(rw0.y);
                float2 a0 = __half22float2(*reinterpret_cast<__half2*>(&v0.x));
                float2 a1 = __half22float2(*reinterpret_cast<__half2*>(&v0.y));
                pa.x = fmaf(wt0, a0.x, pa.x);
                pa.y = fmaf(wt0, a0.y, pa.y);
                pa.z = fmaf(wt0, a1.x, pa.z);
                pa.w = fmaf(wt0, a1.y, pa.w);
            }
            pa.x += pb.x; pa.y += pb.y; pa.z += pb.z; pa.w += pb.w;
            acc.x = fmaf(dc, pa.x, acc.x);
            acc.y = fmaf(dc, pa.y, acc.y);
            acc.z = fmaf(dc, pa.z, acc.z);
            acc.w = fmaf(dc, pa.w, acc.w);
        }
        float4 v;
        v.x = fmaxf(acc.x + b0, 0.f);
        v.y = fmaxf(acc.y + b1, 0.f);
        v.z = fmaxf(acc.z + b2, 0.f);
        v.w = fmaxf(acc.w + b3, 0.f);
        *(float4*)(g_agg + (size_t)n * 128 + c0) = v;
        ss.x += v.x; ss.y += v.y; ss.z += v.z; ss.w += v.w;
        sq.x += v.x * v.x; sq.y += v.y * v.y; sq.z += v.z * v.z; sq.w += v.w * v.w;
    }
    atomicAdd(&st[c0 + 0], ss.x);
    atomicAdd(&st[c0 + 1], ss.y);
    atomicAdd(&st[c0 + 2], ss.z);
    atomicAdd(&st[c0 + 3], ss.w);
    atomicAdd(&st[128 + c0 + 0], sq.x);
    atomicAdd(&st[128 + c0 + 1], sq.y);
    atomicAdd(&st[128 + c0 + 2], sq.z);
    atomicAdd(&st[128 + c0 + 3], sq.w);
    __syncthreads();
    if (tid < 128) atomicAdd(&g_bnsum[2 * layer][tid], st[tid]);
    else atomicAdd(&g_bnsum[2 * layer + 1][tid - 128], st[tid]);
}

// ---------------- final: inline BN-finalize + apply + residual + tail zeroing
__global__ void k_final(const float* __restrict__ x, const float* __restrict__ gamma,
                        const float* __restrict__ beta, float* __restrict__ out) {
    __shared__ float P[256];
    int tid = threadIdx.x;
    int i = blockIdx.x * blockDim.x + tid;
    if (tid < 128) {
        float mu = g_bnsum[2][tid] / (float)NN;
        float var = g_bnsum[3][tid] / (float)NN - mu * mu;
        P[tid]       = mu;
        P[128 + tid] = rsqrtf(var + 1e-5f);
    }
    __syncthreads();
    if (i < NN * 32) {
        int cb = (i & 31) * 4;
        float4 v = ((const float4*)g_agg)[i];
        float4 xv = ((const float4*)x)[i];
        v.x = (v.x - P[cb + 0]) * P[128 + cb + 0] * gamma[cb + 0] + beta[cb + 0] + xv.x;
        v.y = (v.y - P[cb + 1]) * P[128 + cb + 1] * gamma[cb + 1] + beta[cb + 1] + xv.y;
        v.z = (v.z - P[cb + 2]) * P[128 + cb + 2] * gamma[cb + 2] + beta[cb + 2] + xv.z;
        v.w = (v.w - P[cb + 3]) * P[128 + cb + 3] * gamma[cb + 3] + beta[cb + 3] + xv.w;
        ((float4*)out)[i] = v;
    }
    if (i < 3 * NN) {
        (&g_cnt[0][0])[i] = 0;
        (&g_degf[0][0])[i] = 0.f;
    }
    if (i < 256) (&g_bnsum[0][0])[i] = 0.f;
}

// ---------------- launch (fork/join: setup overlaps the MLP) -----------------
extern "C" void kernel_launch(void* const* d_in, const int* in_sizes, int n_in,
                              void* d_out, int out_size) {
    const float* x   = (const float*)d_in[0];
    const int*   e0  = (const int*)d_in[1];
    const int*   e1  = (const int*)d_in[2];
    const int*   e2  = (const int*)d_in[3];
    const float* Wa1 = (const float*)d_in[4];
    const float* ba1 = (const float*)d_in[5];
    const float* Wa2 = (const float*)d_in[6];
    const float* ba2 = (const float*)d_in[7];
    const float* W0  = (const float*)d_in[8];
    const float* b0  = (const float*)d_in[9];
    const float* W1  = (const float*)d_in[10];
    const float* b1  = (const float*)d_in[11];
    const float* g0  = (const float*)d_in[12];
    const float* be0 = (const float*)d_in[13];
    const float* g1  = (const float*)d_in[14];
    const float* be1 = (const float*)d_in[15];
    float* out = (float*)d_out;

    static cudaStream_t s1 = nullptr;
    static cudaEvent_t ev1 = nullptr, ev2 = nullptr;
    if (!s1) {
        cudaStreamCreateWithFlags(&s1, cudaStreamNonBlocking);
        cudaEventCreateWithFlags(&ev1, cudaEventDisableTiming);
        cudaEventCreateWithFlags(&ev2, cudaEventDisableTiming);
    }

    cudaFuncSetAttribute(k_edge_mlp_mma, cudaFuncAttributeMaxDynamicSharedMemorySize,
                         EW_SMEM_BYTES);
    cudaFuncSetAttribute(k_gemm0, cudaFuncAttributeMaxDynamicSharedMemorySize,
                         GM_SMEM_BYTES);
    cudaFuncSetAttribute(k_gemm1, cudaFuncAttributeMaxDynamicSharedMemorySize,
                         GM_SMEM_BYTES);

    // main stream: xh -> MLP
    k_xh<<<(NN * 64 + 255) / 256, 256>>>(x);
    cudaEventRecord(ev1, 0);
    k_edge_mlp_mma<<<MLP_CTAS, 256, EW_SMEM_BYTES>>>(e0, e1, e2, Wa1, ba1, Wa2, ba2);

    // side stream (forked after xh): count -> scan -> gemm0, hidden under MLP
    cudaStreamWaitEvent(s1, ev1, 0);
    k_count<<<(3 * EE + 255) / 256, 256, 0, s1>>>(e0, e1, e2);
    k_scan<<<3, 1024, 0, s1>>>();
    k_gemm0<<<MLP_CTAS, 256, GM_SMEM_BYTES, s1>>>(W0);
    cudaEventRecord(ev2, s1);

    // join, then the serial tail
    cudaStreamWaitEvent(0, ev2, 0);
    k_fill<<<(3 * EE + 255) / 256, 256>>>(e0, e1, e2);
    k_agg<<<AGG_CTAS, 256>>>(b0, 0);
    k_gemm1<<<MLP_CTAS, 256, GM_SMEM_BYTES>>>(W1, g0, be0);
    k_agg<<<AGG_CTAS, 256>>>(b1, 1);
    k_final<<<(NN * 32 + 255) / 256, 256>>>(x, g1, be1, out);
}